// round 16
// baseline (speedup 1.0000x reference)
#include <cuda_runtime.h>
#include <cuda_bf16.h>
#include <cstdint>

#define BB 2
#define LL 2048
#define DD 1024
#define HH 16
#define DHH 64
#define BH (BB*HH)
#define MROWS (BB*LL)           // 4096
#define OUT_ELEMS (MROWS*DD)
#define LN_EPS 1e-5f

// ---------------------------------------------------------------------------
// Static device scratch
// ---------------------------------------------------------------------------
__device__ __nv_bfloat16 g_xq_h[MROWS*DD], g_xq_l[MROWS*DD];
__device__ __nv_bfloat16 g_xk_h[MROWS*DD], g_xk_l[MROWS*DD];
__device__ __nv_bfloat16 g_xv_h[MROWS*DD];
__device__ __nv_bfloat16 g_wq_h[DD*DD], g_wq_l[DD*DD];
__device__ __nv_bfloat16 g_wk_h[DD*DD], g_wk_l[DD*DD];
__device__ __nv_bfloat16 g_wv_h[DD*DD];
__device__ __nv_bfloat16 g_wo_h[DD*DD];
__device__ __nv_bfloat16 g_Qh[MROWS*DD], g_Ql[MROWS*DD];
__device__ __nv_bfloat16 g_Kh[MROWS*DD], g_Kl[MROWS*DD];
__device__ __nv_bfloat16 g_Vth[MROWS*DD];            // [n][c][k], bf16 only
__device__ __nv_bfloat16 g_ctxh[MROWS*DD];           // bf16 only
__device__ float g_part[(long)BH*LL*16];
__device__ float g_rinv[(long)BH*LL];
__device__ float g_proj[MROWS*DD];

// ---------------------------------------------------------------------------
// PTX helpers
// ---------------------------------------------------------------------------
__device__ __forceinline__ uint32_t smem_u32(const void* p) {
    uint32_t a;
    asm("{ .reg .u64 t; cvta.to.shared.u64 t, %1; cvt.u32.u64 %0, t; }" : "=r"(a) : "l"(p));
    return a;
}

#define LDMX4(r0,r1,r2,r3,addr) \
    asm volatile("ldmatrix.sync.aligned.m8n8.x4.shared.b16 {%0,%1,%2,%3}, [%4];" \
        : "=r"(r0), "=r"(r1), "=r"(r2), "=r"(r3) : "r"(addr))

#define MMA_BF16(d, a, b0v, b1v) \
    asm volatile("mma.sync.aligned.m16n8k16.row.col.f32.bf16.bf16.f32 " \
        "{%0,%1,%2,%3},{%4,%5,%6,%7},{%8,%9},{%0,%1,%2,%3};" \
        : "+f"((d)[0]), "+f"((d)[1]), "+f"((d)[2]), "+f"((d)[3]) \
        : "r"((a)[0]), "r"((a)[1]), "r"((a)[2]), "r"((a)[3]), "r"(b0v), "r"(b1v))

__device__ __forceinline__ void cp16(uint32_t dst, const void* src) {
    asm volatile("cp.async.cg.shared.global [%0], [%1], 16;" :: "r"(dst), "l"(src));
}
#define CP_COMMIT() asm volatile("cp.async.commit_group;" ::: "memory")
#define CP_WAIT0()  asm volatile("cp.async.wait_group 0;" ::: "memory")
#define CP_WAIT1()  asm volatile("cp.async.wait_group 1;" ::: "memory")

__device__ __forceinline__ void lda_frag(uint32_t a[4], uint32_t base, int mbase, int ks, int lane) {
    int row = mbase + (lane & 7) + ((lane >> 3) & 1) * 8;
    int col = ks + (lane >> 4) * 8;
    LDMX4(a[0], a[1], a[2], a[3], base + row * 80 + col * 2);
}
__device__ __forceinline__ void ldb_frag(uint32_t b[4], uint32_t base, int nbase, int ks, int lane) {
    int r = lane & 7, gp = lane >> 3;
    int n = nbase + (gp >> 1) * 8 + r;
    int col = ks + (gp & 1) * 8;
    LDMX4(b[0], b[1], b[2], b[3], base + n * 80 + col * 2);
}

__device__ __forceinline__ void load32_async(const __nv_bfloat16* __restrict__ src, long ld,
                                             int R, uint32_t base, int tid) {
    for (int i = tid; i < R * 4; i += 256) {
        int row = i >> 2, q = i & 3;
        cp16(base + row * 80 + q * 16, src + (long)row * ld + q * 8);
    }
}

__device__ __forceinline__ void split2(float v, unsigned short& h, unsigned short& l) {
    __nv_bfloat16 bh = __float2bfloat16(v);
    __nv_bfloat16 bl = __float2bfloat16(v - __bfloat162float(bh));
    h = __bfloat16_as_ushort(bh); l = __bfloat16_as_ushort(bl);
}
__device__ __forceinline__ uint32_t pack_hi(float x, float y) {
    unsigned short hx = __bfloat16_as_ushort(__float2bfloat16(x));
    unsigned short hy = __bfloat16_as_ushort(__float2bfloat16(y));
    return (uint32_t)hx | ((uint32_t)hy << 16);
}

// ---------------------------------------------------------------------------
// fp32 -> bf16 split kernels (value / Wv / Wo need hi only)
// ---------------------------------------------------------------------------
__global__ void __launch_bounds__(256) split_inputs_kernel(
    const float* __restrict__ s0, const float* __restrict__ s1, const float* __restrict__ s2)
{
    const int which = blockIdx.y;
    const float* src = which == 0 ? s0 : which == 1 ? s1 : s2;
    __nv_bfloat16* hi = which == 0 ? g_xq_h : which == 1 ? g_xk_h : g_xv_h;
    __nv_bfloat16* lo = which == 0 ? g_xq_l : g_xk_l;
    long i = (long)blockIdx.x * 256 + threadIdx.x;
    float4 v = reinterpret_cast<const float4*>(src)[i];
    unsigned short h0,h1,h2,h3,l0,l1,l2,l3;
    split2(v.x,h0,l0); split2(v.y,h1,l1); split2(v.z,h2,l2); split2(v.w,h3,l3);
    uint2 uh;
    uh.x = (uint32_t)h0 | ((uint32_t)h1 << 16); uh.y = (uint32_t)h2 | ((uint32_t)h3 << 16);
    reinterpret_cast<uint2*>(hi)[i] = uh;
    if (which < 2) {
        uint2 ul;
        ul.x = (uint32_t)l0 | ((uint32_t)l1 << 16); ul.y = (uint32_t)l2 | ((uint32_t)l3 << 16);
        reinterpret_cast<uint2*>(lo)[i] = ul;
    }
}

__global__ void __launch_bounds__(256) split_weights_kernel(
    const float* __restrict__ s0, const float* __restrict__ s1,
    const float* __restrict__ s2, const float* __restrict__ s3)
{
    const int which = blockIdx.y;
    const float* src = which == 0 ? s0 : which == 1 ? s1 : which == 2 ? s2 : s3;
    __nv_bfloat16* hi = which == 0 ? g_wq_h : which == 1 ? g_wk_h : which == 2 ? g_wv_h : g_wo_h;
    __nv_bfloat16* lo = which == 0 ? g_wq_l : g_wk_l;
    long i = (long)blockIdx.x * 256 + threadIdx.x;
    float4 v = reinterpret_cast<const float4*>(src)[i];
    unsigned short h0,h1,h2,h3,l0,l1,l2,l3;
    split2(v.x,h0,l0); split2(v.y,h1,l1); split2(v.z,h2,l2); split2(v.w,h3,l3);
    uint2 uh;
    uh.x = (uint32_t)h0 | ((uint32_t)h1 << 16); uh.y = (uint32_t)h2 | ((uint32_t)h3 << 16);
    reinterpret_cast<uint2*>(hi)[i] = uh;
    if (which < 2) {
        uint2 ul;
        ul.x = (uint32_t)l0 | ((uint32_t)l1 << 16); ul.y = (uint32_t)l2 | ((uint32_t)l3 << 16);
        reinterpret_cast<uint2*>(lo)[i] = ul;
    }
}

// ---------------------------------------------------------------------------
// 3-pass split GEMM mainloop (block 128x128, BK=32, K=1024), 2-stage 80KB
// ---------------------------------------------------------------------------
#define PROJ_DSMEM (2*40960)
__device__ __forceinline__ void proj_mainloop(
    const __nv_bfloat16* __restrict__ Ah_, const __nv_bfloat16* __restrict__ Al_,
    const __nv_bfloat16* __restrict__ Bh_, const __nv_bfloat16* __restrict__ Bl_,
    uint32_t sb, int tid, int lane, int wm, int wn, float acc[4][4][4])
{
    const int NC = DD / 32;   // 32
    #pragma unroll
    for (int p = 0; p < 2; p++) {
        uint32_t s = sb + p * 40960;
        load32_async(Ah_ + p*32, DD, 128, s,         tid);
        load32_async(Al_ + p*32, DD, 128, s + 10240, tid);
        load32_async(Bh_ + p*32, DD, 128, s + 20480, tid);
        load32_async(Bl_ + p*32, DD, 128, s + 30720, tid);
        CP_COMMIT();
    }
    for (int c = 0; c < NC; c++) {
        CP_WAIT1();
        __syncthreads();
        uint32_t sc = sb + (c & 1) * 40960;
        uint32_t sAh = sc, sAl = sc + 10240, sBh = sc + 20480, sBl = sc + 30720;
        #pragma unroll
        for (int ks = 0; ks < 32; ks += 16) {
            uint32_t ah[4][4], al[4][4], bh[2][4], bl[2][4];
            #pragma unroll
            for (int mf = 0; mf < 4; mf++) {
                lda_frag(ah[mf], sAh, wm + mf*16, ks, lane);
                lda_frag(al[mf], sAl, wm + mf*16, ks, lane);
            }
            ldb_frag(bh[0], sBh, wn,      ks, lane);
            ldb_frag(bh[1], sBh, wn + 16, ks, lane);
            ldb_frag(bl[0], sBl, wn,      ks, lane);
            ldb_frag(bl[1], sBl, wn + 16, ks, lane);
            #pragma unroll
            for (int mf = 0; mf < 4; mf++)
                #pragma unroll
                for (int nf = 0; nf < 4; nf++) {
                    MMA_BF16(acc[mf][nf], ah[mf], bh[nf>>1][(nf&1)*2], bh[nf>>1][(nf&1)*2+1]);
                    MMA_BF16(acc[mf][nf], ah[mf], bl[nf>>1][(nf&1)*2], bl[nf>>1][(nf&1)*2+1]);
                    MMA_BF16(acc[mf][nf], al[mf], bh[nf>>1][(nf&1)*2], bh[nf>>1][(nf&1)*2+1]);
                }
        }
        __syncthreads();
        if (c + 2 < NC) {
            uint32_t sn = sb + (c & 1) * 40960;
            load32_async(Ah_ + (c+2)*32, DD, 128, sn,         tid);
            load32_async(Al_ + (c+2)*32, DD, 128, sn + 10240, tid);
            load32_async(Bh_ + (c+2)*32, DD, 128, sn + 20480, tid);
            load32_async(Bl_ + (c+2)*32, DD, 128, sn + 30720, tid);
            CP_COMMIT();
        } else {
            CP_COMMIT();
        }
    }
}

// ---------------------------------------------------------------------------
// Q/K projections (3-pass, z = 0/1), flat bf16 hi/lo outputs
// ---------------------------------------------------------------------------
__global__ void __launch_bounds__(256, 2) qk_proj_kernel(
    const float* __restrict__ bq, const float* __restrict__ bk)
{
    extern __shared__ __align__(16) char smem[];
    const uint32_t sb = smem_u32(smem);
    const int tid = threadIdx.x, wid = tid >> 5, lane = tid & 31;
    const int row0 = blockIdx.y * 128, col0 = blockIdx.x * 128;
    const int wm = (wid >> 2) * 64, wn = (wid & 3) * 32;
    const int z = blockIdx.z;

    const __nv_bfloat16* Ah_ = (z == 0 ? g_xq_h : g_xk_h) + (long)row0 * DD;
    const __nv_bfloat16* Al_ = (z == 0 ? g_xq_l : g_xk_l) + (long)row0 * DD;
    const __nv_bfloat16* Bh_ = (z == 0 ? g_wq_h : g_wk_h) + (long)col0 * DD;
    const __nv_bfloat16* Bl_ = (z == 0 ? g_wq_l : g_wk_l) + (long)col0 * DD;
    const float* bias = z == 0 ? bq : bk;

    float acc[4][4][4];
    #pragma unroll
    for (int i = 0; i < 4; i++)
        #pragma unroll
        for (int j = 0; j < 4; j++)
            #pragma unroll
            for (int q = 0; q < 4; q++) acc[i][j][q] = 0.f;

    proj_mainloop(Ah_, Al_, Bh_, Bl_, sb, tid, lane, wm, wn, acc);

    const int g = lane >> 2, tq = lane & 3;
    __nv_bfloat16* OutHi = z == 0 ? g_Qh : g_Kh;
    __nv_bfloat16* OutLo = z == 0 ? g_Ql : g_Kl;
    #pragma unroll
    for (int mf = 0; mf < 4; mf++)
        #pragma unroll
        for (int nf = 0; nf < 4; nf++) {
            long r0 = row0 + wm + mf*16 + g, r1 = r0 + 8;
            int  cb = col0 + wn + nf*8 + tq*2;
            float b0 = bias[cb], b1 = bias[cb + 1];
            float v00 = acc[mf][nf][0] + b0, v01 = acc[mf][nf][1] + b1;
            float v10 = acc[mf][nf][2] + b0, v11 = acc[mf][nf][3] + b1;
            unsigned short h0,h1,l0,l1;
            split2(v00,h0,l0); split2(v01,h1,l1);
            *reinterpret_cast<uint32_t*>(OutHi + r0*DD + cb) = (uint32_t)h0 | ((uint32_t)h1<<16);
            *reinterpret_cast<uint32_t*>(OutLo + r0*DD + cb) = (uint32_t)l0 | ((uint32_t)l1<<16);
            split2(v10,h0,l0); split2(v11,h1,l1);
            *reinterpret_cast<uint32_t*>(OutHi + r1*DD + cb) = (uint32_t)h0 | ((uint32_t)h1<<16);
            *reinterpret_cast<uint32_t*>(OutLo + r1*DD + cb) = (uint32_t)l0 | ((uint32_t)l1<<16);
        }
}

// ---------------------------------------------------------------------------
// Single-pass bf16 GEMM (block 128x128, BK=32): V projection & out projection
// mode 0: Vt scatter (bf16), mode 1: fp32 + bias -> g_proj
// Stage = A 10240 + B 10240 = 20480; 2 stages = 40KB
// ---------------------------------------------------------------------------
#define SP_DSMEM (2*20480)
__global__ void __launch_bounds__(256, 2) sp_proj_kernel(
    const __nv_bfloat16* __restrict__ A, const __nv_bfloat16* __restrict__ B,
    const float* __restrict__ bias, int mode)
{
    extern __shared__ __align__(16) char smem[];
    const uint32_t sb = smem_u32(smem);
    const int tid = threadIdx.x, wid = tid >> 5, lane = tid & 31;
    const int row0 = blockIdx.y * 128, col0 = blockIdx.x * 128;
    const int wm = (wid >> 2) * 64, wn = (wid & 3) * 32;

    const __nv_bfloat16* A_ = A + (long)row0 * DD;
    const __nv_bfloat16* B_ = B + (long)col0 * DD;

    float acc[4][4][4];
    #pragma unroll
    for (int i = 0; i < 4; i++)
        #pragma unroll
        for (int j = 0; j < 4; j++)
            #pragma unroll
            for (int q = 0; q < 4; q++) acc[i][j][q] = 0.f;

    const int NC = DD / 32;   // 32
    #pragma unroll
    for (int p = 0; p < 2; p++) {
        uint32_t s = sb + p * 20480;
        load32_async(A_ + p*32, DD, 128, s,         tid);
        load32_async(B_ + p*32, DD, 128, s + 10240, tid);
        CP_COMMIT();
    }
    for (int c = 0; c < NC; c++) {
        CP_WAIT1();
        __syncthreads();
        uint32_t sc = sb + (c & 1) * 20480;
        #pragma unroll
        for (int ks = 0; ks < 32; ks += 16) {
            uint32_t a[4][4], b0[4], b1[4];
            #pragma unroll
            for (int mf = 0; mf < 4; mf++)
                lda_frag(a[mf], sc, wm + mf*16, ks, lane);
            ldb_frag(b0, sc + 10240, wn,      ks, lane);
            ldb_frag(b1, sc + 10240, wn + 16, ks, lane);
            #pragma unroll
            for (int mf = 0; mf < 4; mf++)
                #pragma unroll
                for (int nf = 0; nf < 4; nf++)
                    MMA_BF16(acc[mf][nf], a[mf],
                             (nf < 2 ? b0 : b1)[(nf&1)*2], (nf < 2 ? b0 : b1)[(nf&1)*2+1]);
        }
        __syncthreads();
        if (c + 2 < NC) {
            uint32_t sn = sb + (c & 1) * 20480;
            load32_async(A_ + (c+2)*32, DD, 128, sn,         tid);
            load32_async(B_ + (c+2)*32, DD, 128, sn + 10240, tid);
            CP_COMMIT();
        } else {
            CP_COMMIT();
        }
    }

    const int g = lane >> 2, tq = lane & 3;
    #pragma unroll
    for (int mf = 0; mf < 4; mf++)
        #pragma unroll
        for (int nf = 0; nf < 4; nf++) {
            long r0 = row0 + wm + mf*16 + g, r1 = r0 + 8;
            int  cb = col0 + wn + nf*8 + tq*2;
            float b0 = bias[cb], b1 = bias[cb + 1];
            float v00 = acc[mf][nf][0] + b0, v01 = acc[mf][nf][1] + b1;
            float v10 = acc[mf][nf][2] + b0, v11 = acc[mf][nf][3] + b1;
            if (mode == 1) {
                *reinterpret_cast<float2*>(g_proj + r0 * DD + cb) = make_float2(v00, v01);
                *reinterpret_cast<float2*>(g_proj + r1 * DD + cb) = make_float2(v10, v11);
            } else {
                #pragma unroll
                for (int e = 0; e < 4; e++) {
                    long rr = (e < 2) ? r0 : r1;
                    int  cc = cb + (e & 1);
                    float v = (e==0)?v00:(e==1)?v01:(e==2)?v10:v11;
                    long f = rr * DD + cc;
                    long n = f >> 17, rem = f & 131071;
                    long kpos = rem >> 6, cdim = rem & 63;
                    g_Vth[n * 131072 + cdim * 2048 + kpos] = __float2bfloat16(v);
                }
            }
        }
}

// ---------------------------------------------------------------------------
// Scores: 128x128 tile per head, K=64, 3-pass. exp staged in smem,
// coalesced streaming writes + row partial sums.
// ---------------------------------------------------------------------------
#define SC_DSMEM (2*40960)
__global__ void __launch_bounds__(256, 2) scores_mma_kernel(
    float* __restrict__ attn, float* __restrict__ part)
{
    extern __shared__ __align__(16) char smem[];
    __shared__ float srow[128][4];
    const uint32_t sb = smem_u32(smem);
    const int tid = threadIdx.x, wid = tid >> 5, lane = tid & 31;
    const int z = blockIdx.z;
    const int row0 = blockIdx.y * 128, col0 = blockIdx.x * 128;
    const int wm = (wid >> 2) * 64, wn = (wid & 3) * 32;
    const long hoff = (long)z * LL * DHH;

    float acc[4][4][4];
    #pragma unroll
    for (int i = 0; i < 4; i++)
        #pragma unroll
        for (int j = 0; j < 4; j++)
            #pragma unroll
            for (int q = 0; q < 4; q++) acc[i][j][q] = 0.f;

    #pragma unroll
    for (int c = 0; c < 2; c++) {
        uint32_t s = sb + c * 40960;
        load32_async(g_Qh + hoff + (long)row0 * 64 + c*32, 64, 128, s,         tid);
        load32_async(g_Ql + hoff + (long)row0 * 64 + c*32, 64, 128, s + 10240, tid);
        load32_async(g_Kh + hoff + (long)col0 * 64 + c*32, 64, 128, s + 20480, tid);
        load32_async(g_Kl + hoff + (long)col0 * 64 + c*32, 64, 128, s + 30720, tid);
        CP_COMMIT();
    }

    #pragma unroll
    for (int c = 0; c < 2; c++) {
        if (c == 0) CP_WAIT1(); else CP_WAIT0();
        __syncthreads();
        uint32_t sc = sb + c * 40960;
        uint32_t sAh = sc, sAl = sc + 10240, sBh = sc + 20480, sBl = sc + 30720;
        #pragma unroll
        for (int ks = 0; ks < 32; ks += 16) {
            uint32_t ah[4][4], al[4][4], bh[2][4], bl[2][4];
            #pragma unroll
            for (int mf = 0; mf < 4; mf++) {
                lda_frag(ah[mf], sAh, wm + mf*16, ks, lane);
                lda_frag(al[mf], sAl, wm + mf*16, ks, lane);
            }
            ldb_frag(bh[0], sBh, wn,      ks, lane);
            ldb_frag(bh[1], sBh, wn + 16, ks, lane);
            ldb_frag(bl[0], sBl, wn,      ks, lane);
            ldb_frag(bl[1], sBl, wn + 16, ks, lane);
            #pragma unroll
            for (int mf = 0; mf < 4; mf++)
                #pragma unroll
                for (int nf = 0; nf < 4; nf++) {
                    MMA_BF16(acc[mf][nf], ah[mf], bh[nf>>1][(nf&1)*2], bh[nf>>1][(nf&1)*2+1]);
                    MMA_BF16(acc[mf][nf], ah[mf], bl[nf>>1][(nf&1)*2], bl[nf>>1][(nf&1)*2+1]);
                    MMA_BF16(acc[mf][nf], al[mf], bh[nf>>1][(nf&1)*2], bh[nf>>1][(nf&1)*2+1]);
                }
        }
    }

    __syncthreads();
    float* stg = reinterpret_cast<float*>(smem);
    const int g = lane >> 2, tq = lane & 3;
    #pragma unroll
    for (int mf = 0; mf < 4; mf++) {
        float s0 = 0.f, s1 = 0.f;
        int lr0 = wm + mf*16 + g, lr1 = lr0 + 8;
        #pragma unroll
        for (int nf = 0; nf < 4; nf++) {
            int cb = wn + nf*8 + tq*2;
            float e00 = __expf(acc[mf][nf][0] * 0.125f);
            float e01 = __expf(acc[mf][nf][1] * 0.125f);
            float e10 = __expf(acc[mf][nf][2] * 0.125f);
            float e11 = __expf(acc[mf][nf][3] * 0.125f);
            s0 += e00 + e01; s1 += e10 + e11;
            stg[lr0 * 132 + cb] = e00; stg[lr0 * 132 + cb + 1] = e01;
            stg[lr1 * 132 + cb] = e10; stg[lr1 * 132 + cb + 1] = e11;
        }
        s0 += __shfl_xor_sync(0xffffffffu, s0, 1);
        s0 += __shfl_xor_sync(0xffffffffu, s0, 2);
        s1 += __shfl_xor_sync(0xffffffffu, s1, 1);
        s1 += __shfl_xor_sync(0xffffffffu, s1, 2);
        if (tq == 0) {
            srow[lr0][wid & 3] = s0;
            srow[lr1][wid & 3] = s1;
        }
    }
    __syncthreads();

    float* ap = attn + (long)z * LL * LL + (long)row0 * LL + col0;
    for (int i = tid; i < 128 * 32; i += 256) {
        int row = i >> 5, q = i & 31;
        float4 v = *reinterpret_cast<const float4*>(stg + row * 132 + q * 4);
        __stcs(reinterpret_cast<float4*>(ap + (long)row * LL + q * 4), v);
    }
    if (tid < 128) {
        float t = srow[tid][0] + srow[tid][1] + srow[tid][2] + srow[tid][3];
        part[((long)z * LL + row0 + tid) * 16 + blockIdx.x] = t;
    }
}

// ---------------------------------------------------------------------------
// Row reciprocal
// ---------------------------------------------------------------------------
__global__ void __launch_bounds__(256) rowinv_kernel(const float* __restrict__ part,
                                                     float* __restrict__ rinv) {
    long i = (long)blockIdx.x * 256 + threadIdx.x;
    float s = 0.f;
    #pragma unroll
    for (int t = 0; t < 16; t++) s += part[i * 16 + t];
    rinv[i] = 1.0f / s;
}

// ---------------------------------------------------------------------------
// AV single-pass bf16: normalize attn chunk (smem-staged via cp.async),
// stream write-back, pack bf16 P, MMA vs V (bf16). Block 128x64.
// Dyn smem: A(10240) + 3 stages x (ATTN 16384 + Vh 5120 = 21504) = 74752
// ---------------------------------------------------------------------------
#define AV_DSMEM (10240 + 3*21504)
__global__ void __launch_bounds__(256, 2) av_mma_kernel(
    float* __restrict__ attn, const float* __restrict__ rinv)
{
    extern __shared__ __align__(16) char smem[];
    __shared__ float rvs[128];
    const uint32_t sb = smem_u32(smem);
    const int tid = threadIdx.x, wid = tid >> 5, lane = tid & 31;
    const int z = blockIdx.y;
    const int row0 = blockIdx.x * 128;
    const int wm = (wid >> 2) * 64, wn = (wid & 3) * 16;

    float* ab = attn + (long)z * LL * LL + (long)row0 * LL;
    const __nv_bfloat16* vh = g_Vth + (long)z * LL * DHH;

    if (tid < 128) rvs[tid] = rinv[(long)z * LL + row0 + tid];

    float acc[4][2][4];
    #pragma unroll
    for (int i = 0; i < 4; i++)
        #pragma unroll
        for (int j = 0; j < 2; j++)
            #pragma unroll
            for (int q = 0; q < 4; q++) acc[i][j][q] = 0.f;

    const uint32_t AH = sb;
    const int NC = LL / 32;   // 64

    #pragma unroll
    for (int p = 0; p < 2; p++) {
        uint32_t s = sb + 10240 + p * 21504;
        long goff = (long)p * 32;
        for (int i = tid; i < 1024; i += 256) {
            int row = i >> 3, q = i & 7;
            cp16(s + row * 128 + q * 16, ab + (long)row * LL + goff + q * 4);
        }
        load32_async(vh + goff, LL, 64, s + 16384, tid);
        CP_COMMIT();
    }

    for (int c = 0; c < NC; c++) {
        CP_WAIT1();
        __syncthreads();
        if (c + 2 < NC) {
            uint32_t sn = sb + 10240 + ((c + 2) % 3) * 21504;
            long goff = (long)(c + 2) * 32;
            for (int i = tid; i < 1024; i += 256) {
                int row = i >> 3, q = i & 7;
                cp16(sn + row * 128 + q * 16, ab + (long)row * LL + goff + q * 4);
            }
            load32_async(vh + goff, LL, 64, sn + 16384, tid);
            CP_COMMIT();
        } else {
            CP_COMMIT();
        }
        uint32_t sc = sb + 10240 + (c % 3) * 21504;
        char* stg = smem + (sc - sb);

        for (int i = tid; i < 1024; i += 256) {
            int row = i >> 3, q = i & 7;
            float4 v = *reinterpret_cast<const float4*>(stg + row * 128 + q * 16);
            float r = rvs[row];
            v.x *= r; v.y *= r; v.z *= r; v.w *= r;
            __stcs(reinterpret_cast<float4*>(ab + (long)row * LL + (long)c * 32 + q * 4), v);
            uint2 uh;
            uh.x = pack_hi(v.x, v.y);
            uh.y = pack_hi(v.z, v.w);
            *reinterpret_cast<uint2*>(smem + row * 80 + q * 8) = uh;
        }
        __syncthreads();

        uint32_t sBh = sc + 16384;
        #pragma unroll
        for (int ks = 0; ks < 32; ks += 16) {
            uint32_t a[4][4], bv[4];
            #pragma unroll
            for (int mf = 0; mf < 4; mf++)
                lda_frag(a[mf], AH, wm + mf*16, ks, lane);
            ldb_frag(bv, sBh, wn, ks, lane);
            #pragma unroll
            for (int mf = 0; mf < 4; mf++)
                #pragma unroll
                for (int nf = 0; nf < 2; nf++)
                    MMA_BF16(acc[mf][nf], a[mf], bv[nf*2], bv[nf*2+1]);
        }
    }

    const int g = lane >> 2, tq = lane & 3;
    #pragma unroll
    for (int mf = 0; mf < 4; mf++)
        #pragma unroll
        for (int nf = 0; nf < 2; nf++) {
            long r0 = row0 + wm + mf*16 + g, r1 = r0 + 8;
            int cb = wn + nf*8 + tq*2;
            long o0 = (long)z * LL * DHH + r0 * 64 + cb;
            long o1 = (long)z * LL * DHH + r1 * 64 + cb;
            *reinterpret_cast<uint32_t*>(g_ctxh + o0) = pack_hi(acc[mf][nf][0], acc[mf][nf][1]);
            *reinterpret_cast<uint32_t*>(g_ctxh + o1) = pack_hi(acc[mf][nf][2], acc[mf][nf][3]);
        }
}

// ---------------------------------------------------------------------------
// Residual + LayerNorm
// ---------------------------------------------------------------------------
__device__ __forceinline__ float warp_sum(float v) {
    #pragma unroll
    for (int o = 16; o > 0; o >>= 1) v += __shfl_xor_sync(0xffffffffu, v, o);
    return v;
}

__global__ void __launch_bounds__(256) ln_kernel(
    const float* __restrict__ resid,
    const float* __restrict__ gamma, const float* __restrict__ beta,
    float* __restrict__ out)
{
    const long row = blockIdx.x;
    const int tid = threadIdx.x, lane = tid & 31, wid = tid >> 5;
    __shared__ float red[8];

    float4 x = reinterpret_cast<const float4*>(g_proj + row * DD)[tid];
    float4 r = reinterpret_cast<const float4*>(resid + row * DD)[tid];
    x.x += r.x; x.y += r.y; x.z += r.z; x.w += r.w;

    float s = warp_sum(x.x + x.y + x.z + x.w);
    if (lane == 0) red[wid] = s;
    __syncthreads();
    if (wid == 0) {
        float t = (lane < 8) ? red[lane] : 0.f;
        t = warp_sum(t);
        if (lane == 0) red[0] = t;
    }
    __syncthreads();
    const float mu = red[0] * (1.0f / DD);
    __syncthreads();

    float dx = x.x - mu, dy = x.y - mu, dz = x.z - mu, dw = x.w - mu;
    float ss = warp_sum(dx*dx + dy*dy + dz*dz + dw*dw);
    if (lane == 0) red[wid] = ss;
    __syncthreads();
    if (wid == 0) {
        float t = (lane < 8) ? red[lane] : 0.f;
        t = warp_sum(t);
        if (lane == 0) red[0] = t;
    }
    __syncthreads();
    const float rs = rsqrtf(red[0] * (1.0f / DD) + LN_EPS);

    float4 gm = reinterpret_cast<const float4*>(gamma)[tid];
    float4 be = reinterpret_cast<const float4*>(beta)[tid];
    float4 o;
    o.x = dx * rs * gm.x + be.x;
    o.y = dy * rs * gm.y + be.y;
    o.z = dz * rs * gm.z + be.z;
    o.w = dw * rs * gm.w + be.w;
    reinterpret_cast<float4*>(out + row * DD)[tid] = o;
}

// ---------------------------------------------------------------------------
// Launch
// ---------------------------------------------------------------------------
extern "C" void kernel_launch(void* const* d_in, const int* in_sizes, int n_in,
                              void* d_out, int out_size)
{
    const float* query = (const float*)d_in[0];
    const float* key   = (const float*)d_in[1];
    const float* value = (const float*)d_in[2];
    const float* Wq = (const float*)d_in[3];
    const float* bq = (const float*)d_in[4];
    const float* Wk = (const float*)d_in[5];
    const float* bk = (const float*)d_in[6];
    const float* Wv = (const float*)d_in[7];
    const float* bv = (const float*)d_in[8];
    const float* Wo = (const float*)d_in[9];
    const float* bo = (const float*)d_in[10];
    const float* gamma = (const float*)d_in[11];
    const float* beta  = (const float*)d_in[12];

    float* out  = (float*)d_out;
    float* attn = out + OUT_ELEMS;

    float *part, *rinv;
    cudaGetSymbolAddress((void**)&part, g_part);
    cudaGetSymbolAddress((void**)&rinv, g_rinv);
    __nv_bfloat16 *xvh, *wvh, *ctxh, *woh;
    cudaGetSymbolAddress((void**)&xvh, g_xv_h);
    cudaGetSymbolAddress((void**)&wvh, g_wv_h);
    cudaGetSymbolAddress((void**)&ctxh, g_ctxh);
    cudaGetSymbolAddress((void**)&woh, g_wo_h);

    cudaFuncSetAttribute(qk_proj_kernel,    cudaFuncAttributeMaxDynamicSharedMemorySize, PROJ_DSMEM);
    cudaFuncSetAttribute(sp_proj_kernel,    cudaFuncAttributeMaxDynamicSharedMemorySize, SP_DSMEM);
    cudaFuncSetAttribute(scores_mma_kernel, cudaFuncAttributeMaxDynamicSharedMemorySize, SC_DSMEM);
    cudaFuncSetAttribute(av_mma_kernel,     cudaFuncAttributeMaxDynamicSharedMemorySize, AV_DSMEM);

    // 1) fp32 -> bf16 splits
    dim3 gsi(OUT_ELEMS / 1024, 3);
    split_inputs_kernel<<<gsi, 256>>>(query, key, value);
    dim3 gsw(DD * DD / 1024, 4);
    split_weights_kernel<<<gsw, 256>>>(Wq, Wk, Wv, Wo);

    // 2) Q/K projections (3-pass) + V projection (single-pass, Vt scatter)
    dim3 gqk(DD/128, MROWS/128, 2);
    qk_proj_kernel<<<gqk, 256, PROJ_DSMEM>>>(bq, bk);
    dim3 gsp(DD/128, MROWS/128);
    sp_proj_kernel<<<gsp, 256, SP_DSMEM>>>(xvh, wvh, bv, 0);

    // 3) Scores + exp + partial sums (3-pass)
    dim3 gs(LL/128, LL/128, BH);
    scores_mma_kernel<<<gs, 256, SC_DSMEM>>>(attn, part);

    // 4) Row reciprocals
    rowinv_kernel<<<(BH*LL)/256, 256>>>(part, rinv);

    // 5) AV single-pass (normalizes attention in place, writes bf16 ctx)
    dim3 ga(LL/128, BH);
    av_mma_kernel<<<ga, 256, AV_DSMEM>>>(attn, rinv);

    // 6) Out projection (single-pass) + residual + LN
    sp_proj_kernel<<<gsp, 256, SP_DSMEM>>>(ctxh, woh, bo, 1);
    ln_kernel<<<MROWS, 256>>>(query, gamma, beta, out);
}

// round 17
// speedup vs baseline: 1.2999x; 1.2999x over previous
#include <cuda_runtime.h>
#include <cuda_bf16.h>
#include <cstdint>

#define BB 2
#define LL 2048
#define DD 1024
#define HH 16
#define DHH 64
#define BH (BB*HH)
#define MROWS (BB*LL)           // 4096
#define OUT_ELEMS (MROWS*DD)
#define LN_EPS 1e-5f

// ---------------------------------------------------------------------------
// Static device scratch
// ---------------------------------------------------------------------------
__device__ __nv_bfloat16 g_xq_h[MROWS*DD], g_xq_l[MROWS*DD];
__device__ __nv_bfloat16 g_xk_h[MROWS*DD], g_xk_l[MROWS*DD];
__device__ __nv_bfloat16 g_xv_h[MROWS*DD];
__device__ __nv_bfloat16 g_wq_h[DD*DD], g_wq_l[DD*DD];
__device__ __nv_bfloat16 g_wk_h[DD*DD], g_wk_l[DD*DD];
__device__ __nv_bfloat16 g_wv_h[DD*DD];
__device__ __nv_bfloat16 g_wo_h[DD*DD];
__device__ __nv_bfloat16 g_Qh[MROWS*DD], g_Ql[MROWS*DD];
__device__ __nv_bfloat16 g_Kh[MROWS*DD], g_Kl[MROWS*DD];
__device__ __nv_bfloat16 g_Vth[MROWS*DD], g_Vtl[MROWS*DD];  // [n][c][k]
__device__ __nv_bfloat16 g_ctxh[MROWS*DD], g_ctxl[MROWS*DD];
__device__ float g_part[(long)BH*LL*16];
__device__ float g_rinv[(long)BH*LL];
__device__ float g_proj[MROWS*DD];

// ---------------------------------------------------------------------------
// PTX helpers
// ---------------------------------------------------------------------------
__device__ __forceinline__ uint32_t smem_u32(const void* p) {
    uint32_t a;
    asm("{ .reg .u64 t; cvta.to.shared.u64 t, %1; cvt.u32.u64 %0, t; }" : "=r"(a) : "l"(p));
    return a;
}

#define LDMX4(r0,r1,r2,r3,addr) \
    asm volatile("ldmatrix.sync.aligned.m8n8.x4.shared.b16 {%0,%1,%2,%3}, [%4];" \
        : "=r"(r0), "=r"(r1), "=r"(r2), "=r"(r3) : "r"(addr))

#define MMA_BF16(d, a, b0v, b1v) \
    asm volatile("mma.sync.aligned.m16n8k16.row.col.f32.bf16.bf16.f32 " \
        "{%0,%1,%2,%3},{%4,%5,%6,%7},{%8,%9},{%0,%1,%2,%3};" \
        : "+f"((d)[0]), "+f"((d)[1]), "+f"((d)[2]), "+f"((d)[3]) \
        : "r"((a)[0]), "r"((a)[1]), "r"((a)[2]), "r"((a)[3]), "r"(b0v), "r"(b1v))

__device__ __forceinline__ void cp16(uint32_t dst, const void* src) {
    asm volatile("cp.async.cg.shared.global [%0], [%1], 16;" :: "r"(dst), "l"(src));
}
#define CP_COMMIT() asm volatile("cp.async.commit_group;" ::: "memory")
#define CP_WAIT0()  asm volatile("cp.async.wait_group 0;" ::: "memory")
#define CP_WAIT1()  asm volatile("cp.async.wait_group 1;" ::: "memory")

__device__ __forceinline__ void lda_frag(uint32_t a[4], uint32_t base, int mbase, int ks, int lane) {
    int row = mbase + (lane & 7) + ((lane >> 3) & 1) * 8;
    int col = ks + (lane >> 4) * 8;
    LDMX4(a[0], a[1], a[2], a[3], base + row * 80 + col * 2);
}
__device__ __forceinline__ void ldb_frag(uint32_t b[4], uint32_t base, int nbase, int ks, int lane) {
    int r = lane & 7, gp = lane >> 3;
    int n = nbase + (gp >> 1) * 8 + r;
    int col = ks + (gp & 1) * 8;
    LDMX4(b[0], b[1], b[2], b[3], base + n * 80 + col * 2);
}

__device__ __forceinline__ void load32_async(const __nv_bfloat16* __restrict__ src, long ld,
                                             int R, uint32_t base, int tid) {
    for (int i = tid; i < R * 4; i += 256) {
        int row = i >> 2, q = i & 3;
        cp16(base + row * 80 + q * 16, src + (long)row * ld + q * 8);
    }
}

__device__ __forceinline__ void split2(float v, unsigned short& h, unsigned short& l) {
    __nv_bfloat16 bh = __float2bfloat16(v);
    __nv_bfloat16 bl = __float2bfloat16(v - __bfloat162float(bh));
    h = __bfloat16_as_ushort(bh); l = __bfloat16_as_ushort(bl);
}

// ---------------------------------------------------------------------------
// fp32 -> bf16 split kernels (value / Wv / Wo need hi only)
// ---------------------------------------------------------------------------
__global__ void __launch_bounds__(256) split_inputs_kernel(
    const float* __restrict__ s0, const float* __restrict__ s1, const float* __restrict__ s2)
{
    const int which = blockIdx.y;
    const float* src = which == 0 ? s0 : which == 1 ? s1 : s2;
    __nv_bfloat16* hi = which == 0 ? g_xq_h : which == 1 ? g_xk_h : g_xv_h;
    __nv_bfloat16* lo = which == 0 ? g_xq_l : g_xk_l;
    long i = (long)blockIdx.x * 256 + threadIdx.x;
    float4 v = reinterpret_cast<const float4*>(src)[i];
    unsigned short h0,h1,h2,h3,l0,l1,l2,l3;
    split2(v.x,h0,l0); split2(v.y,h1,l1); split2(v.z,h2,l2); split2(v.w,h3,l3);
    uint2 uh;
    uh.x = (uint32_t)h0 | ((uint32_t)h1 << 16); uh.y = (uint32_t)h2 | ((uint32_t)h3 << 16);
    reinterpret_cast<uint2*>(hi)[i] = uh;
    if (which < 2) {
        uint2 ul;
        ul.x = (uint32_t)l0 | ((uint32_t)l1 << 16); ul.y = (uint32_t)l2 | ((uint32_t)l3 << 16);
        reinterpret_cast<uint2*>(lo)[i] = ul;
    }
}

__global__ void __launch_bounds__(256) split_weights_kernel(
    const float* __restrict__ s0, const float* __restrict__ s1,
    const float* __restrict__ s2, const float* __restrict__ s3)
{
    const int which = blockIdx.y;
    const float* src = which == 0 ? s0 : which == 1 ? s1 : which == 2 ? s2 : s3;
    __nv_bfloat16* hi = which == 0 ? g_wq_h : which == 1 ? g_wk_h : which == 2 ? g_wv_h : g_wo_h;
    __nv_bfloat16* lo = which == 0 ? g_wq_l : g_wk_l;
    long i = (long)blockIdx.x * 256 + threadIdx.x;
    float4 v = reinterpret_cast<const float4*>(src)[i];
    unsigned short h0,h1,h2,h3,l0,l1,l2,l3;
    split2(v.x,h0,l0); split2(v.y,h1,l1); split2(v.z,h2,l2); split2(v.w,h3,l3);
    uint2 uh;
    uh.x = (uint32_t)h0 | ((uint32_t)h1 << 16); uh.y = (uint32_t)h2 | ((uint32_t)h3 << 16);
    reinterpret_cast<uint2*>(hi)[i] = uh;
    if (which < 2) {
        uint2 ul;
        ul.x = (uint32_t)l0 | ((uint32_t)l1 << 16); ul.y = (uint32_t)l2 | ((uint32_t)l3 << 16);
        reinterpret_cast<uint2*>(lo)[i] = ul;
    }
}

// ---------------------------------------------------------------------------
// 3-pass split GEMM mainloop (block 128x128, BK=32, K=1024), 2-stage 80KB
// ---------------------------------------------------------------------------
#define PROJ_DSMEM (2*40960)
__device__ __forceinline__ void proj_mainloop(
    const __nv_bfloat16* __restrict__ Ah_, const __nv_bfloat16* __restrict__ Al_,
    const __nv_bfloat16* __restrict__ Bh_, const __nv_bfloat16* __restrict__ Bl_,
    uint32_t sb, int tid, int lane, int wm, int wn, float acc[4][4][4])
{
    const int NC = DD / 32;   // 32
    #pragma unroll
    for (int p = 0; p < 2; p++) {
        uint32_t s = sb + p * 40960;
        load32_async(Ah_ + p*32, DD, 128, s,         tid);
        load32_async(Al_ + p*32, DD, 128, s + 10240, tid);
        load32_async(Bh_ + p*32, DD, 128, s + 20480, tid);
        load32_async(Bl_ + p*32, DD, 128, s + 30720, tid);
        CP_COMMIT();
    }
    for (int c = 0; c < NC; c++) {
        CP_WAIT1();
        __syncthreads();
        uint32_t sc = sb + (c & 1) * 40960;
        uint32_t sAh = sc, sAl = sc + 10240, sBh = sc + 20480, sBl = sc + 30720;
        #pragma unroll
        for (int ks = 0; ks < 32; ks += 16) {
            uint32_t ah[4][4], al[4][4], bh[2][4], bl[2][4];
            #pragma unroll
            for (int mf = 0; mf < 4; mf++) {
                lda_frag(ah[mf], sAh, wm + mf*16, ks, lane);
                lda_frag(al[mf], sAl, wm + mf*16, ks, lane);
            }
            ldb_frag(bh[0], sBh, wn,      ks, lane);
            ldb_frag(bh[1], sBh, wn + 16, ks, lane);
            ldb_frag(bl[0], sBl, wn,      ks, lane);
            ldb_frag(bl[1], sBl, wn + 16, ks, lane);
            #pragma unroll
            for (int mf = 0; mf < 4; mf++)
                #pragma unroll
                for (int nf = 0; nf < 4; nf++) {
                    MMA_BF16(acc[mf][nf], ah[mf], bh[nf>>1][(nf&1)*2], bh[nf>>1][(nf&1)*2+1]);
                    MMA_BF16(acc[mf][nf], ah[mf], bl[nf>>1][(nf&1)*2], bl[nf>>1][(nf&1)*2+1]);
                    MMA_BF16(acc[mf][nf], al[mf], bh[nf>>1][(nf&1)*2], bh[nf>>1][(nf&1)*2+1]);
                }
        }
        __syncthreads();
        if (c + 2 < NC) {
            uint32_t sn = sb + (c & 1) * 40960;
            load32_async(Ah_ + (c+2)*32, DD, 128, sn,         tid);
            load32_async(Al_ + (c+2)*32, DD, 128, sn + 10240, tid);
            load32_async(Bh_ + (c+2)*32, DD, 128, sn + 20480, tid);
            load32_async(Bl_ + (c+2)*32, DD, 128, sn + 30720, tid);
            CP_COMMIT();
        } else {
            CP_COMMIT();
        }
    }
}

// ---------------------------------------------------------------------------
// Q/K projections (3-pass, z = 0/1), flat bf16 hi/lo outputs
// ---------------------------------------------------------------------------
__global__ void __launch_bounds__(256, 2) qk_proj_kernel(
    const float* __restrict__ bq, const float* __restrict__ bk)
{
    extern __shared__ __align__(16) char smem[];
    const uint32_t sb = smem_u32(smem);
    const int tid = threadIdx.x, wid = tid >> 5, lane = tid & 31;
    const int row0 = blockIdx.y * 128, col0 = blockIdx.x * 128;
    const int wm = (wid >> 2) * 64, wn = (wid & 3) * 32;
    const int z = blockIdx.z;

    const __nv_bfloat16* Ah_ = (z == 0 ? g_xq_h : g_xk_h) + (long)row0 * DD;
    const __nv_bfloat16* Al_ = (z == 0 ? g_xq_l : g_xk_l) + (long)row0 * DD;
    const __nv_bfloat16* Bh_ = (z == 0 ? g_wq_h : g_wk_h) + (long)col0 * DD;
    const __nv_bfloat16* Bl_ = (z == 0 ? g_wq_l : g_wk_l) + (long)col0 * DD;
    const float* bias = z == 0 ? bq : bk;

    float acc[4][4][4];
    #pragma unroll
    for (int i = 0; i < 4; i++)
        #pragma unroll
        for (int j = 0; j < 4; j++)
            #pragma unroll
            for (int q = 0; q < 4; q++) acc[i][j][q] = 0.f;

    proj_mainloop(Ah_, Al_, Bh_, Bl_, sb, tid, lane, wm, wn, acc);

    const int g = lane >> 2, tq = lane & 3;
    __nv_bfloat16* OutHi = z == 0 ? g_Qh : g_Kh;
    __nv_bfloat16* OutLo = z == 0 ? g_Ql : g_Kl;
    #pragma unroll
    for (int mf = 0; mf < 4; mf++)
        #pragma unroll
        for (int nf = 0; nf < 4; nf++) {
            long r0 = row0 + wm + mf*16 + g, r1 = r0 + 8;
            int  cb = col0 + wn + nf*8 + tq*2;
            float b0 = bias[cb], b1 = bias[cb + 1];
            float v00 = acc[mf][nf][0] + b0, v01 = acc[mf][nf][1] + b1;
            float v10 = acc[mf][nf][2] + b0, v11 = acc[mf][nf][3] + b1;
            unsigned short h0,h1,l0,l1;
            split2(v00,h0,l0); split2(v01,h1,l1);
            *reinterpret_cast<uint32_t*>(OutHi + r0*DD + cb) = (uint32_t)h0 | ((uint32_t)h1<<16);
            *reinterpret_cast<uint32_t*>(OutLo + r0*DD + cb) = (uint32_t)l0 | ((uint32_t)l1<<16);
            split2(v10,h0,l0); split2(v11,h1,l1);
            *reinterpret_cast<uint32_t*>(OutHi + r1*DD + cb) = (uint32_t)h0 | ((uint32_t)h1<<16);
            *reinterpret_cast<uint32_t*>(OutLo + r1*DD + cb) = (uint32_t)l0 | ((uint32_t)l1<<16);
        }
}

// ---------------------------------------------------------------------------
// Single-pass bf16 GEMM (block 128x128, BK=32): V projection & out projection
// mode 0: Vt scatter (writes BOTH hi and residual-lo so AV stays 3-pass)
// mode 1: fp32 + bias -> g_proj
// ---------------------------------------------------------------------------
#define SP_DSMEM (2*20480)
__global__ void __launch_bounds__(256, 2) sp_proj_kernel(
    const __nv_bfloat16* __restrict__ A, const __nv_bfloat16* __restrict__ B,
    const float* __restrict__ bias, int mode)
{
    extern __shared__ __align__(16) char smem[];
    const uint32_t sb = smem_u32(smem);
    const int tid = threadIdx.x, wid = tid >> 5, lane = tid & 31;
    const int row0 = blockIdx.y * 128, col0 = blockIdx.x * 128;
    const int wm = (wid >> 2) * 64, wn = (wid & 3) * 32;

    const __nv_bfloat16* A_ = A + (long)row0 * DD;
    const __nv_bfloat16* B_ = B + (long)col0 * DD;

    float acc[4][4][4];
    #pragma unroll
    for (int i = 0; i < 4; i++)
        #pragma unroll
        for (int j = 0; j < 4; j++)
            #pragma unroll
            for (int q = 0; q < 4; q++) acc[i][j][q] = 0.f;

    const int NC = DD / 32;   // 32
    #pragma unroll
    for (int p = 0; p < 2; p++) {
        uint32_t s = sb + p * 20480;
        load32_async(A_ + p*32, DD, 128, s,         tid);
        load32_async(B_ + p*32, DD, 128, s + 10240, tid);
        CP_COMMIT();
    }
    for (int c = 0; c < NC; c++) {
        CP_WAIT1();
        __syncthreads();
        uint32_t sc = sb + (c & 1) * 20480;
        #pragma unroll
        for (int ks = 0; ks < 32; ks += 16) {
            uint32_t a[4][4], b0[4], b1[4];
            #pragma unroll
            for (int mf = 0; mf < 4; mf++)
                lda_frag(a[mf], sc, wm + mf*16, ks, lane);
            ldb_frag(b0, sc + 10240, wn,      ks, lane);
            ldb_frag(b1, sc + 10240, wn + 16, ks, lane);
            #pragma unroll
            for (int mf = 0; mf < 4; mf++)
                #pragma unroll
                for (int nf = 0; nf < 4; nf++)
                    MMA_BF16(acc[mf][nf], a[mf],
                             (nf < 2 ? b0 : b1)[(nf&1)*2], (nf < 2 ? b0 : b1)[(nf&1)*2+1]);
        }
        __syncthreads();
        if (c + 2 < NC) {
            uint32_t sn = sb + (c & 1) * 20480;
            load32_async(A_ + (c+2)*32, DD, 128, sn,         tid);
            load32_async(B_ + (c+2)*32, DD, 128, sn + 10240, tid);
            CP_COMMIT();
        } else {
            CP_COMMIT();
        }
    }

    const int g = lane >> 2, tq = lane & 3;
    #pragma unroll
    for (int mf = 0; mf < 4; mf++)
        #pragma unroll
        for (int nf = 0; nf < 4; nf++) {
            long r0 = row0 + wm + mf*16 + g, r1 = r0 + 8;
            int  cb = col0 + wn + nf*8 + tq*2;
            float b0 = bias[cb], b1 = bias[cb + 1];
            float v00 = acc[mf][nf][0] + b0, v01 = acc[mf][nf][1] + b1;
            float v10 = acc[mf][nf][2] + b0, v11 = acc[mf][nf][3] + b1;
            if (mode == 1) {
                *reinterpret_cast<float2*>(g_proj + r0 * DD + cb) = make_float2(v00, v01);
                *reinterpret_cast<float2*>(g_proj + r1 * DD + cb) = make_float2(v10, v11);
            } else {
                #pragma unroll
                for (int e = 0; e < 4; e++) {
                    long rr = (e < 2) ? r0 : r1;
                    int  cc = cb + (e & 1);
                    float v = (e==0)?v00:(e==1)?v01:(e==2)?v10:v11;
                    unsigned short h, l; split2(v, h, l);
                    long f = rr * DD + cc;
                    long n = f >> 17, rem = f & 131071;
                    long kpos = rem >> 6, cdim = rem & 63;
                    long addr = n * 131072 + cdim * 2048 + kpos;
                    g_Vth[addr] = __ushort_as_bfloat16(h);
                    g_Vtl[addr] = __ushort_as_bfloat16(l);
                }
            }
        }
}

// ---------------------------------------------------------------------------
// Scores: 128x128 tile per head, K=64, 3-pass. exp staged in smem,
// coalesced writes + row partial sums.  (identical to R13)
// ---------------------------------------------------------------------------
#define SC_DSMEM (2*40960)
__global__ void __launch_bounds__(256, 2) scores_mma_kernel(
    float* __restrict__ attn, float* __restrict__ part)
{
    extern __shared__ __align__(16) char smem[];
    __shared__ float srow[128][4];
    const uint32_t sb = smem_u32(smem);
    const int tid = threadIdx.x, wid = tid >> 5, lane = tid & 31;
    const int z = blockIdx.z;
    const int row0 = blockIdx.y * 128, col0 = blockIdx.x * 128;
    const int wm = (wid >> 2) * 64, wn = (wid & 3) * 32;
    const long hoff = (long)z * LL * DHH;

    float acc[4][4][4];
    #pragma unroll
    for (int i = 0; i < 4; i++)
        #pragma unroll
        for (int j = 0; j < 4; j++)
            #pragma unroll
            for (int q = 0; q < 4; q++) acc[i][j][q] = 0.f;

    #pragma unroll
    for (int c = 0; c < 2; c++) {
        uint32_t s = sb + c * 40960;
        load32_async(g_Qh + hoff + (long)row0 * 64 + c*32, 64, 128, s,         tid);
        load32_async(g_Ql + hoff + (long)row0 * 64 + c*32, 64, 128, s + 10240, tid);
        load32_async(g_Kh + hoff + (long)col0 * 64 + c*32, 64, 128, s + 20480, tid);
        load32_async(g_Kl + hoff + (long)col0 * 64 + c*32, 64, 128, s + 30720, tid);
        CP_COMMIT();
    }

    #pragma unroll
    for (int c = 0; c < 2; c++) {
        if (c == 0) CP_WAIT1(); else CP_WAIT0();
        __syncthreads();
        uint32_t sc = sb + c * 40960;
        uint32_t sAh = sc, sAl = sc + 10240, sBh = sc + 20480, sBl = sc + 30720;
        #pragma unroll
        for (int ks = 0; ks < 32; ks += 16) {
            uint32_t ah[4][4], al[4][4], bh[2][4], bl[2][4];
            #pragma unroll
            for (int mf = 0; mf < 4; mf++) {
                lda_frag(ah[mf], sAh, wm + mf*16, ks, lane);
                lda_frag(al[mf], sAl, wm + mf*16, ks, lane);
            }
            ldb_frag(bh[0], sBh, wn,      ks, lane);
            ldb_frag(bh[1], sBh, wn + 16, ks, lane);
            ldb_frag(bl[0], sBl, wn,      ks, lane);
            ldb_frag(bl[1], sBl, wn + 16, ks, lane);
            #pragma unroll
            for (int mf = 0; mf < 4; mf++)
                #pragma unroll
                for (int nf = 0; nf < 4; nf++) {
                    MMA_BF16(acc[mf][nf], ah[mf], bh[nf>>1][(nf&1)*2], bh[nf>>1][(nf&1)*2+1]);
                    MMA_BF16(acc[mf][nf], ah[mf], bl[nf>>1][(nf&1)*2], bl[nf>>1][(nf&1)*2+1]);
                    MMA_BF16(acc[mf][nf], al[mf], bh[nf>>1][(nf&1)*2], bh[nf>>1][(nf&1)*2+1]);
                }
        }
    }

    __syncthreads();
    float* stg = reinterpret_cast<float*>(smem);
    const int g = lane >> 2, tq = lane & 3;
    #pragma unroll
    for (int mf = 0; mf < 4; mf++) {
        float s0 = 0.f, s1 = 0.f;
        int lr0 = wm + mf*16 + g, lr1 = lr0 + 8;
        #pragma unroll
        for (int nf = 0; nf < 4; nf++) {
            int cb = wn + nf*8 + tq*2;
            float e00 = __expf(acc[mf][nf][0] * 0.125f);
            float e01 = __expf(acc[mf][nf][1] * 0.125f);
            float e10 = __expf(acc[mf][nf][2] * 0.125f);
            float e11 = __expf(acc[mf][nf][3] * 0.125f);
            s0 += e00 + e01; s1 += e10 + e11;
            stg[lr0 * 132 + cb] = e00; stg[lr0 * 132 + cb + 1] = e01;
            stg[lr1 * 132 + cb] = e10; stg[lr1 * 132 + cb + 1] = e11;
        }
        s0 += __shfl_xor_sync(0xffffffffu, s0, 1);
        s0 += __shfl_xor_sync(0xffffffffu, s0, 2);
        s1 += __shfl_xor_sync(0xffffffffu, s1, 1);
        s1 += __shfl_xor_sync(0xffffffffu, s1, 2);
        if (tq == 0) {
            srow[lr0][wid & 3] = s0;
            srow[lr1][wid & 3] = s1;
        }
    }
    __syncthreads();

    float* ap = attn + (long)z * LL * LL + (long)row0 * LL + col0;
    for (int i = tid; i < 128 * 32; i += 256) {
        int row = i >> 5, q = i & 31;
        float4 v = *reinterpret_cast<const float4*>(stg + row * 132 + q * 4);
        *reinterpret_cast<float4*>(ap + (long)row * LL + q * 4) = v;
    }
    if (tid < 128) {
        float t = srow[tid][0] + srow[tid][1] + srow[tid][2] + srow[tid][3];
        part[((long)z * LL + row0 + tid) * 16 + blockIdx.x] = t;
    }
}

// ---------------------------------------------------------------------------
// Row reciprocal
// ---------------------------------------------------------------------------
__global__ void __launch_bounds__(256) rowinv_kernel(const float* __restrict__ part,
                                                     float* __restrict__ rinv) {
    long i = (long)blockIdx.x * 256 + threadIdx.x;
    float s = 0.f;
    #pragma unroll
    for (int t = 0; t < 16; t++) s += part[i * 16 + t];
    rinv[i] = 1.0f / s;
}

// ---------------------------------------------------------------------------
// AV, 3-stage cp.async (identical to R13): normalize attn chunk, write back,
// split, 3-pass MMA vs Vt hi/lo.
// ---------------------------------------------------------------------------
#define AV_DSMEM (20480 + 3*26624)
__global__ void __launch_bounds__(256, 2) av_mma_kernel(
    float* __restrict__ attn, const float* __restrict__ rinv)
{
    extern __shared__ __align__(16) char smem[];
    __shared__ float rvs[128];
    const uint32_t sb = smem_u32(smem);
    const int tid = threadIdx.x, wid = tid >> 5, lane = tid & 31;
    const int z = blockIdx.y;
    const int row0 = blockIdx.x * 128;
    const int wm = (wid >> 2) * 64, wn = (wid & 3) * 16;

    float* ab = attn + (long)z * LL * LL + (long)row0 * LL;
    const __nv_bfloat16* vh = g_Vth + (long)z * LL * DHH;
    const __nv_bfloat16* vl = g_Vtl + (long)z * LL * DHH;

    if (tid < 128) rvs[tid] = rinv[(long)z * LL + row0 + tid];

    float acc[4][2][4];
    #pragma unroll
    for (int i = 0; i < 4; i++)
        #pragma unroll
        for (int j = 0; j < 2; j++)
            #pragma unroll
            for (int q = 0; q < 4; q++) acc[i][j][q] = 0.f;

    const uint32_t AH = sb, AL = sb + 10240;
    const int NC = LL / 32;   // 64

    #pragma unroll
    for (int p = 0; p < 2; p++) {
        uint32_t s = sb + 20480 + p * 26624;
        long goff = (long)p * 32;
        for (int i = tid; i < 1024; i += 256) {
            int row = i >> 3, q = i & 7;
            cp16(s + row * 128 + q * 16, ab + (long)row * LL + goff + q * 4);
        }
        load32_async(vh + goff, LL, 64, s + 16384, tid);
        load32_async(vl + goff, LL, 64, s + 21504, tid);
        CP_COMMIT();
    }

    for (int c = 0; c < NC; c++) {
        CP_WAIT1();
        __syncthreads();
        if (c + 2 < NC) {
            uint32_t sn = sb + 20480 + ((c + 2) % 3) * 26624;
            long goff = (long)(c + 2) * 32;
            for (int i = tid; i < 1024; i += 256) {
                int row = i >> 3, q = i & 7;
                cp16(sn + row * 128 + q * 16, ab + (long)row * LL + goff + q * 4);
            }
            load32_async(vh + goff, LL, 64, sn + 16384, tid);
            load32_async(vl + goff, LL, 64, sn + 21504, tid);
            CP_COMMIT();
        } else {
            CP_COMMIT();
        }
        uint32_t sc = sb + 20480 + (c % 3) * 26624;
        char* stg = smem + (sc - sb);

        for (int i = tid; i < 1024; i += 256) {
            int row = i >> 3, q = i & 7;
            float4 v = *reinterpret_cast<const float4*>(stg + row * 128 + q * 16);
            float r = rvs[row];
            v.x *= r; v.y *= r; v.z *= r; v.w *= r;
            *reinterpret_cast<float4*>(ab + (long)row * LL + (long)c * 32 + q * 4) = v;
            unsigned short h0,h1,h2,h3,l0,l1,l2,l3;
            split2(v.x,h0,l0); split2(v.y,h1,l1); split2(v.z,h2,l2); split2(v.w,h3,l3);
            uint2 uh, ul;
            uh.x = (uint32_t)h0 | ((uint32_t)h1 << 16);
            uh.y = (uint32_t)h2 | ((uint32_t)h3 << 16);
            ul.x = (uint32_t)l0 | ((uint32_t)l1 << 16);
            ul.y = (uint32_t)l2 | ((uint32_t)l3 << 16);
            *reinterpret_cast<uint2*>(smem + row * 80 + q * 8)         = uh;
            *reinterpret_cast<uint2*>(smem + 10240 + row * 80 + q * 8) = ul;
        }
        __syncthreads();

        uint32_t sBh = sc + 16384, sBl = sc + 21504;
        #pragma unroll
        for (int ks = 0; ks < 32; ks += 16) {
            uint32_t ah[4][4], al[4][4], bh[4], bl[4];
            #pragma unroll
            for (int mf = 0; mf < 4; mf++) {
                lda_frag(ah[mf], AH, wm + mf*16, ks, lane);
                lda_frag(al[mf], AL, wm + mf*16, ks, lane);
            }
            ldb_frag(bh, sBh, wn, ks, lane);
            ldb_frag(bl, sBl, wn, ks, lane);
            #pragma unroll
            for (int mf = 0; mf < 4; mf++)
                #pragma unroll
                for (int nf = 0; nf < 2; nf++) {
                    MMA_BF16(acc[mf][nf], ah[mf], bh[nf*2], bh[nf*2+1]);
                    MMA_BF16(acc[mf][nf], ah[mf], bl[nf*2], bl[nf*2+1]);
                    MMA_BF16(acc[mf][nf], al[mf], bh[nf*2], bh[nf*2+1]);
                }
        }
    }

    const int g = lane >> 2, tq = lane & 3;
    #pragma unroll
    for (int mf = 0; mf < 4; mf++)
        #pragma unroll
        for (int nf = 0; nf < 2; nf++) {
            long r0 = row0 + wm + mf*16 + g, r1 = r0 + 8;
            int cb = wn + nf*8 + tq*2;
            unsigned short h0,h1,l0,l1;
            long o0 = (long)z * LL * DHH + r0 * 64 + cb;
            long o1 = (long)z * LL * DHH + r1 * 64 + cb;
            split2(acc[mf][nf][0], h0, l0); split2(acc[mf][nf][1], h1, l1);
            *reinterpret_cast<uint32_t*>(g_ctxh + o0) = (uint32_t)h0 | ((uint32_t)h1<<16);
            *reinterpret_cast<uint32_t*>(g_ctxl + o0) = (uint32_t)l0 | ((uint32_t)l1<<16);
            split2(acc[mf][nf][2], h0, l0); split2(acc[mf][nf][3], h1, l1);
            *reinterpret_cast<uint32_t*>(g_ctxh + o1) = (uint32_t)h0 | ((uint32_t)h1<<16);
            *reinterpret_cast<uint32_t*>(g_ctxl + o1) = (uint32_t)l0 | ((uint32_t)l1<<16);
        }
}

// ---------------------------------------------------------------------------
// Residual + LayerNorm
// ---------------------------------------------------------------------------
__device__ __forceinline__ float warp_sum(float v) {
    #pragma unroll
    for (int o = 16; o > 0; o >>= 1) v += __shfl_xor_sync(0xffffffffu, v, o);
    return v;
}

__global__ void __launch_bounds__(256) ln_kernel(
    const float* __restrict__ resid,
    const float* __restrict__ gamma, const float* __restrict__ beta,
    float* __restrict__ out)
{
    const long row = blockIdx.x;
    const int tid = threadIdx.x, lane = tid & 31, wid = tid >> 5;
    __shared__ float red[8];

    float4 x = reinterpret_cast<const float4*>(g_proj + row * DD)[tid];
    float4 r = reinterpret_cast<const float4*>(resid + row * DD)[tid];
    x.x += r.x; x.y += r.y; x.z += r.z; x.w += r.w;

    float s = warp_sum(x.x + x.y + x.z + x.w);
    if (lane == 0) red[wid] = s;
    __syncthreads();
    if (wid == 0) {
        float t = (lane < 8) ? red[lane] : 0.f;
        t = warp_sum(t);
        if (lane == 0) red[0] = t;
    }
    __syncthreads();
    const float mu = red[0] * (1.0f / DD);
    __syncthreads();

    float dx = x.x - mu, dy = x.y - mu, dz = x.z - mu, dw = x.w - mu;
    float ss = warp_sum(dx*dx + dy*dy + dz*dz + dw*dw);
    if (lane == 0) red[wid] = ss;
    __syncthreads();
    if (wid == 0) {
        float t = (lane < 8) ? red[lane] : 0.f;
        t = warp_sum(t);
        if (lane == 0) red[0] = t;
    }
    __syncthreads();
    const float rs = rsqrtf(red[0] * (1.0f / DD) + LN_EPS);

    float4 gm = reinterpret_cast<const float4*>(gamma)[tid];
    float4 be = reinterpret_cast<const float4*>(beta)[tid];
    float4 o;
    o.x = dx * rs * gm.x + be.x;
    o.y = dy * rs * gm.y + be.y;
    o.z = dz * rs * gm.z + be.z;
    o.w = dw * rs * gm.w + be.w;
    reinterpret_cast<float4*>(out + row * DD)[tid] = o;
}

// ---------------------------------------------------------------------------
// Launch
// ---------------------------------------------------------------------------
extern "C" void kernel_launch(void* const* d_in, const int* in_sizes, int n_in,
                              void* d_out, int out_size)
{
    const float* query = (const float*)d_in[0];
    const float* key   = (const float*)d_in[1];
    const float* value = (const float*)d_in[2];
    const float* Wq = (const float*)d_in[3];
    const float* bq = (const float*)d_in[4];
    const float* Wk = (const float*)d_in[5];
    const float* bk = (const float*)d_in[6];
    const float* Wv = (const float*)d_in[7];
    const float* bv = (const float*)d_in[8];
    const float* Wo = (const float*)d_in[9];
    const float* bo = (const float*)d_in[10];
    const float* gamma = (const float*)d_in[11];
    const float* beta  = (const float*)d_in[12];

    float* out  = (float*)d_out;
    float* attn = out + OUT_ELEMS;

    float *part, *rinv;
    cudaGetSymbolAddress((void**)&part, g_part);
    cudaGetSymbolAddress((void**)&rinv, g_rinv);
    __nv_bfloat16 *xvh, *wvh, *ctxh, *woh;
    cudaGetSymbolAddress((void**)&xvh, g_xv_h);
    cudaGetSymbolAddress((void**)&wvh, g_wv_h);
    cudaGetSymbolAddress((void**)&ctxh, g_ctxh);
    cudaGetSymbolAddress((void**)&woh, g_wo_h);

    cudaFuncSetAttribute(qk_proj_kernel,    cudaFuncAttributeMaxDynamicSharedMemorySize, PROJ_DSMEM);
    cudaFuncSetAttribute(sp_proj_kernel,    cudaFuncAttributeMaxDynamicSharedMemorySize, SP_DSMEM);
    cudaFuncSetAttribute(scores_mma_kernel, cudaFuncAttributeMaxDynamicSharedMemorySize, SC_DSMEM);
    cudaFuncSetAttribute(av_mma_kernel,     cudaFuncAttributeMaxDynamicSharedMemorySize, AV_DSMEM);

    // 1) fp32 -> bf16 splits
    dim3 gsi(OUT_ELEMS / 1024, 3);
    split_inputs_kernel<<<gsi, 256>>>(query, key, value);
    dim3 gsw(DD * DD / 1024, 4);
    split_weights_kernel<<<gsw, 256>>>(Wq, Wk, Wv, Wo);

    // 2) Q/K projections (3-pass) + V projection (single-pass, Vt hi+lo scatter)
    dim3 gqk(DD/128, MROWS/128, 2);
    qk_proj_kernel<<<gqk, 256, PROJ_DSMEM>>>(bq, bk);
    dim3 gsp(DD/128, MROWS/128);
    sp_proj_kernel<<<gsp, 256, SP_DSMEM>>>(xvh, wvh, bv, 0);

    // 3) Scores + exp + partial sums (3-pass)
    dim3 gs(LL/128, LL/128, BH);
    scores_mma_kernel<<<gs, 256, SC_DSMEM>>>(attn, part);

    // 4) Row reciprocals
    rowinv_kernel<<<(BH*LL)/256, 256>>>(part, rinv);

    // 5) AV (3-pass, identical to R13)
    dim3 ga(LL/128, BH);
    av_mma_kernel<<<ga, 256, AV_DSMEM>>>(attn, rinv);

    // 6) Out projection (single-pass) + residual + LN
    sp_proj_kernel<<<gsp, 256, SP_DSMEM>>>(ctxh, woh, bo, 1);
    ln_kernel<<<MROWS, 256>>>(query, gamma, beta, out);
}